// round 1
// baseline (speedup 1.0000x reference)
#include <cuda_runtime.h>
#include <math.h>

// Shapes (fixed by the problem)
//  K=128 rows, N=2048 nodes, D=512
#define KK 128
#define NNODES 2048
#define DD 512

// Scratch (device globals — no allocations allowed)
__device__ float g_cq[KK * DD];        // context @ Wq^T
__device__ float g_qt[KK * DD];        // g_cq @ Wk  (effective query in x-space)
__device__ float g_compat[KK * NNODES];
__device__ int   g_mask_i32;           // 1 if mask serialized as int32, 0 if uint8

// ---------------------------------------------------------------------------
// Mask dtype probe: read the first 65536 int32 words (= 262144 bytes, valid
// under EITHER serialization). If every word is 0 or 1 -> int32 mask;
// random packed bytes make that probability ~(1/8)^65536 under uint8.
// Deterministic given inputs.
// ---------------------------------------------------------------------------
__global__ void detect_mask_kernel(const int* __restrict__ m) {
    __shared__ int bad;
    if (threadIdx.x == 0) bad = 0;
    __syncthreads();
    int local = 0;
    for (int idx = threadIdx.x; idx < 65536; idx += blockDim.x) {
        int v = m[idx];
        if (v != 0 && v != 1) local = 1;
    }
    if (local) bad = 1;
    __syncthreads();
    if (threadIdx.x == 0) g_mask_i32 = bad ? 0 : 1;
}

// ---------------------------------------------------------------------------
// Small GEMMs. Out[128,512] = A[128,512] * op(B[512,512])
//   STAGE1==false : A = ctx (param),  B = Wq, out = g_cq,  out[k,n]=sum_m A[k,m]*B[n,m]  (NT)
//   STAGE1==true  : A = g_cq,        B = Wk, out = g_qt,  out[k,n]=sum_m A[k,m]*B[m,n]  (NN)
// Grid: 32 blocks of 16 output columns; 256 threads.
// ---------------------------------------------------------------------------
template<bool STAGE1>
__global__ void __launch_bounds__(256) gemm_small(const float* __restrict__ Ain,
                                                  const float* __restrict__ B) {
    __shared__ float As[128][64];   // 32KB: all 128 rows x 64 reduction cols
    __shared__ float Bs[16][65];    // padded: conflict-free column reads

    const float* A  = STAGE1 ? g_cq : Ain;
    float*      Out = STAGE1 ? g_qt : g_cq;

    const int t  = threadIdx.x;
    const int n0 = blockIdx.x * 16;
    const int nl = t & 15;          // output column within tile
    const int kb = (t >> 4) * 8;    // 8 output rows per thread

    float acc[8];
#pragma unroll
    for (int j = 0; j < 8; ++j) acc[j] = 0.f;

    for (int mt = 0; mt < DD; mt += 64) {
        // Load As (128x64) with float4, coalesced
#pragma unroll
        for (int s = 0; s < 8; ++s) {
            int idx = t + s * 256;          // 0..2047 float4s
            int r = idx >> 4, c4 = idx & 15;
            float4 v = *reinterpret_cast<const float4*>(A + r * DD + mt + c4 * 4);
            *reinterpret_cast<float4*>(&As[r][c4 * 4]) = v;
        }
        // Load Bs (16x64)
#pragma unroll
        for (int s = 0; s < 4; ++s) {
            int idx = t + s * 256;          // 0..1023
            if (!STAGE1) {                  // NT: B[n,m]
                int e = idx >> 6, c = idx & 63;
                Bs[e][c] = B[(n0 + e) * DD + mt + c];
            } else {                        // NN: B[m,n]
                int c = idx >> 4, e = idx & 15;
                Bs[e][c] = B[(mt + c) * DD + n0 + e];
            }
        }
        __syncthreads();

#pragma unroll 4
        for (int c = 0; c < 64; ++c) {
            float b = Bs[nl][c];
#pragma unroll
            for (int j = 0; j < 8; ++j) acc[j] += As[kb + j][c] * b;
        }
        __syncthreads();
    }

#pragma unroll
    for (int j = 0; j < 8; ++j)
        Out[(kb + j) * DD + n0 + nl] = acc[j];
}

// ---------------------------------------------------------------------------
// Big streaming kernel: compat[k,i] = tanh(clip(qt[k] . x[k,i], -10, 10)) / sqrt(D)
// Grid: 1024 blocks (k = b>>3, 256 i per block), 256 threads = 8 warps,
// 32 rows per warp. Warp-collective dot: 4x float4 streaming loads per lane.
// ---------------------------------------------------------------------------
__global__ void __launch_bounds__(256) compat_kernel(const float* __restrict__ node) {
    const int b    = blockIdx.x;
    const int k    = b >> 3;
    const int lane = threadIdx.x & 31;
    const int i0   = (b & 7) * 256 + (threadIdx.x >> 5) * 32;

    const float4* q4 = reinterpret_cast<const float4*>(g_qt + k * DD);
    const float4 q0 = q4[lane];
    const float4 q1 = q4[32 + lane];
    const float4 q2 = q4[64 + lane];
    const float4 q3 = q4[96 + lane];

    float res = 0.f;
#pragma unroll 2
    for (int ii = 0; ii < 32; ++ii) {
        const int i = i0 + ii;
        const float4* p = reinterpret_cast<const float4*>(node)
                        + ((size_t)(k * NNODES + i) << 7);   // *128 float4 = 512 floats
        float4 v0 = __ldcs(p + lane);
        float4 v1 = __ldcs(p + 32 + lane);
        float4 v2 = __ldcs(p + 64 + lane);
        float4 v3 = __ldcs(p + 96 + lane);
        float a = v0.x * q0.x + v0.y * q0.y + v0.z * q0.z + v0.w * q0.w;
        a += v1.x * q1.x + v1.y * q1.y + v1.z * q1.z + v1.w * q1.w;
        a += v2.x * q2.x + v2.y * q2.y + v2.z * q2.z + v2.w * q2.w;
        a += v3.x * q3.x + v3.y * q3.y + v3.z * q3.z + v3.w * q3.w;
#pragma unroll
        for (int off = 16; off; off >>= 1)
            a += __shfl_xor_sync(0xffffffffu, a, off);
        if (lane == ii) {
            float c = fminf(10.f, fmaxf(-10.f, a));
            res = tanhf(c) * 0.04419417382415922f;   // 1/sqrt(512)
        }
    }
    g_compat[k * NNODES + i0 + lane] = res;          // coalesced
}

// ---------------------------------------------------------------------------
// Masked softmax per row (128 blocks x 256 threads, 8 elems/thread)
// ---------------------------------------------------------------------------
__global__ void __launch_bounds__(256) softmax_kernel(const void* __restrict__ maskp,
                                                      float* __restrict__ out) {
    __shared__ float sc[NNODES];
    __shared__ float red[8];

    const int k = blockIdx.x;
    const int t = threadIdx.x;
    const int lane = t & 31;
    const int warp = t >> 5;
    const bool mi32 = (g_mask_i32 != 0);
    const int* m32 = reinterpret_cast<const int*>(maskp);
    const unsigned char* m8 = reinterpret_cast<const unsigned char*>(maskp);

    float mx = -INFINITY;
#pragma unroll
    for (int s = 0; s < 8; ++s) {
        int i = t + s * 256;
        bool msk = mi32 ? (m32[k * NNODES + i] != 0) : (m8[k * NNODES + i] != 0);
        float v = msk ? -INFINITY : g_compat[k * NNODES + i];
        sc[i] = v;
        mx = fmaxf(mx, v);
    }
#pragma unroll
    for (int off = 16; off; off >>= 1)
        mx = fmaxf(mx, __shfl_xor_sync(0xffffffffu, mx, off));
    if (lane == 0) red[warp] = mx;
    __syncthreads();
    if (t < 32) {
        float v = (t < 8) ? red[t] : -INFINITY;
#pragma unroll
        for (int off = 4; off; off >>= 1)
            v = fmaxf(v, __shfl_xor_sync(0xffffffffu, v, off));
        if (t == 0) red[0] = v;
    }
    __syncthreads();
    mx = red[0];
    __syncthreads();   // protect red[] before reuse

    float sum = 0.f;
#pragma unroll
    for (int s = 0; s < 8; ++s) {
        int i = t + s * 256;
        float v = sc[i];
        float e = (v == -INFINITY) ? 0.f : expf(v - mx);
        sc[i] = e;
        sum += e;
    }
#pragma unroll
    for (int off = 16; off; off >>= 1)
        sum += __shfl_xor_sync(0xffffffffu, sum, off);
    if (lane == 0) red[warp] = sum;
    __syncthreads();
    if (t < 32) {
        float v = (t < 8) ? red[t] : 0.f;
#pragma unroll
        for (int off = 4; off; off >>= 1)
            v += __shfl_xor_sync(0xffffffffu, v, off);
        if (t == 0) red[0] = v;
    }
    __syncthreads();
    const float inv = 1.0f / red[0];
#pragma unroll
    for (int s = 0; s < 8; ++s) {
        int i = t + s * 256;
        out[k * NNODES + i] = sc[i] * inv;
    }
}

// ---------------------------------------------------------------------------
// Launch. Inputs (metadata order): context_embedding, node_embeddings, mask,
// Wq, Wk, Wv. Output: float [128, 2048].
// ---------------------------------------------------------------------------
extern "C" void kernel_launch(void* const* d_in, const int* in_sizes, int n_in,
                              void* d_out, int out_size) {
    const float* ctx  = (const float*)d_in[0];
    const float* node = (const float*)d_in[1];
    const void*  mask = d_in[2];
    const float* Wq   = (const float*)d_in[3];
    const float* Wk   = (const float*)d_in[4];
    float* out = (float*)d_out;
    (void)in_sizes; (void)n_in; (void)out_size;

    detect_mask_kernel<<<1, 256>>>((const int*)mask);
    gemm_small<false><<<32, 256>>>(ctx, Wq);     // g_cq = ctx @ Wq^T
    gemm_small<true ><<<32, 256>>>(nullptr, Wk); // g_qt = g_cq @ Wk
    compat_kernel<<<KK * 8, 256>>>(node);        // the HBM-bound pass
    softmax_kernel<<<KK, 256>>>(mask, out);
}

// round 6
// speedup vs baseline: 1.1244x; 1.1244x over previous
#include <cuda_runtime.h>
#include <math.h>

#define KK 128
#define NNODES 2048
#define DD 512

__device__ float g_cq[KK * DD];        // context @ Wq^T
__device__ float g_qt[KK * DD];        // g_cq @ Wk
__device__ float g_compat[KK * NNODES];
__device__ int   g_mask_i32;

// ---------------------------------------------------------------------------
// Mask dtype probe (16384 int32 words = 64KB: in-bounds under either dtype)
// ---------------------------------------------------------------------------
__global__ void detect_mask_kernel(const int* __restrict__ m) {
    __shared__ int bad;
    if (threadIdx.x == 0) bad = 0;
    __syncthreads();
    int local = 0;
    for (int idx = threadIdx.x; idx < 16384; idx += blockDim.x) {
        int v = m[idx];
        if (v != 0 && v != 1) local = 1;
    }
    if (local) bad = 1;
    __syncthreads();
    if (threadIdx.x == 0) g_mask_i32 = bad ? 0 : 1;
}

// ---------------------------------------------------------------------------
// Projection GEMMs, issue-lean version.
// Out[128,512]: STAGE1==false: out = ctx @ Wq^T (NT). STAGE1==true: out = g_cq @ Wk (NN).
// Grid 128 = 8 k-tiles(16) x 16 n-tiles(32). Block 256 threads (8 warps).
// Warp w owns k rows {2w, 2w+1}; lane = n within 32-wide tile. 2 outputs/thread.
// Inner step: 2 broadcast LDS (As) + 1 conflict-free LDS (Bs) + 2 FFMA.
// ---------------------------------------------------------------------------
template<bool STAGE1>
__global__ void __launch_bounds__(256) proj_gemm(const float* __restrict__ Ain,
                                                 const float* __restrict__ B) {
    __shared__ float As[16][129];
    __shared__ float Bs[32][129];

    const float* A  = STAGE1 ? g_cq : Ain;
    float*      Out = STAGE1 ? g_qt : g_cq;

    const int t    = threadIdx.x;
    const int lane = t & 31;
    const int w    = t >> 5;
    const int kt   = (blockIdx.x >> 4) * 16;   // k-tile base
    const int n0   = (blockIdx.x & 15) * 32;   // n-tile base
    const int k0   = kt + 2 * w;

    float acc0 = 0.f, acc1 = 0.f;

    for (int mt = 0; mt < DD; mt += 128) {
        // As: 16 x 128  (2048 floats, 8 per thread), coalesced rows
#pragma unroll
        for (int s = 0; s < 8; ++s) {
            int idx = t + s * 256;       // 0..2047
            int r = idx >> 7, c = idx & 127;
            As[r][c] = A[(kt + r) * DD + mt + c];
        }
        // Bs: 32 x 128  (4096 floats, 16 per thread)
#pragma unroll
        for (int s = 0; s < 16; ++s) {
            int idx = t + s * 256;       // 0..4095
            if (!STAGE1) {               // NT: Bs[n][m] = Wq[n0+n][mt+m], coalesced in m
                int n = idx >> 7, c = idx & 127;
                Bs[n][c] = B[(n0 + n) * DD + mt + c];
            } else {                     // NN: Bs[n][m] = Wk[mt+m][n0+n], coalesced in n
                int n = idx & 31, c = idx >> 5;
                Bs[n][c] = B[(mt + c) * DD + n0 + n];
            }
        }
        __syncthreads();

#pragma unroll 8
        for (int m = 0; m < 128; ++m) {
            float b  = Bs[lane][m];
            acc0 += As[2 * w][m] * b;
            acc1 += As[2 * w + 1][m] * b;
        }
        __syncthreads();
    }

    Out[(k0    ) * DD + n0 + lane] = acc0;
    Out[(k0 + 1) * DD + n0 + lane] = acc1;
}

// ---------------------------------------------------------------------------
// Streaming compat: compat[k,i] = tanh(clip(qt[k].x[k,i], -10,10)) / sqrt(D)
// Grid 1024 (k = b>>3), 256 threads = 8 warps, 32 nodes per warp.
// Per node: 4 LDG.128/lane + 16 FFMA + 1 STS partial; then one smem
// transpose row-sum per 32 nodes (no dependent shuffle chains).
// ---------------------------------------------------------------------------
__global__ void __launch_bounds__(256) compat_kernel(const float* __restrict__ node) {
    __shared__ float part[8][32][33];   // [warp][node][lane], +1 pad

    const int b    = blockIdx.x;
    const int k    = b >> 3;
    const int lane = threadIdx.x & 31;
    const int w    = threadIdx.x >> 5;
    const int i0   = (b & 7) * 256 + w * 32;

    const float4* q4 = reinterpret_cast<const float4*>(g_qt + k * DD);
    const float4 q0 = q4[lane];
    const float4 q1 = q4[32 + lane];
    const float4 q2 = q4[64 + lane];
    const float4 q3 = q4[96 + lane];

    const float4* base = reinterpret_cast<const float4*>(node)
                       + ((size_t)(k * NNODES + i0) << 7);   // *128 float4/node

#pragma unroll 4
    for (int ii = 0; ii < 32; ++ii) {
        const float4* p = base + ((size_t)ii << 7);
        float4 v0 = __ldcs(p + lane);
        float4 v1 = __ldcs(p + 32 + lane);
        float4 v2 = __ldcs(p + 64 + lane);
        float4 v3 = __ldcs(p + 96 + lane);
        float a0 = v0.x * q0.x + v0.y * q0.y + v0.z * q0.z + v0.w * q0.w;
        float a1 = v1.x * q1.x + v1.y * q1.y + v1.z * q1.z + v1.w * q1.w;
        float a2 = v2.x * q2.x + v2.y * q2.y + v2.z * q2.z + v2.w * q2.w;
        float a3 = v3.x * q3.x + v3.y * q3.y + v3.z * q3.z + v3.w * q3.w;
        part[w][ii][lane] = (a0 + a1) + (a2 + a3);
    }
    __syncwarp();

    // Lane l reduces node l's 32 partials: bank (l + j) % 32 — conflict-free.
    float s0 = 0.f, s1 = 0.f, s2 = 0.f, s3 = 0.f;
#pragma unroll
    for (int j = 0; j < 32; j += 4) {
        s0 += part[w][lane][j];
        s1 += part[w][lane][j + 1];
        s2 += part[w][lane][j + 2];
        s3 += part[w][lane][j + 3];
    }
    float a = (s0 + s1) + (s2 + s3);
    float c = fminf(10.f, fmaxf(-10.f, a));
    g_compat[k * NNODES + i0 + lane] = tanhf(c) * 0.04419417382415922f; // 1/sqrt(512)
}

// ---------------------------------------------------------------------------
// Masked softmax per row
// ---------------------------------------------------------------------------
__global__ void __launch_bounds__(256) softmax_kernel(const void* __restrict__ maskp,
                                                      float* __restrict__ out) {
    __shared__ float sc[NNODES];
    __shared__ float red[8];

    const int k = blockIdx.x;
    const int t = threadIdx.x;
    const int lane = t & 31;
    const int warp = t >> 5;
    const bool mi32 = (g_mask_i32 != 0);
    const int* m32 = reinterpret_cast<const int*>(maskp);
    const unsigned char* m8 = reinterpret_cast<const unsigned char*>(maskp);

    float mx = -INFINITY;
#pragma unroll
    for (int s = 0; s < 8; ++s) {
        int i = t + s * 256;
        bool msk = mi32 ? (m32[k * NNODES + i] != 0) : (m8[k * NNODES + i] != 0);
        float v = msk ? -INFINITY : g_compat[k * NNODES + i];
        sc[i] = v;
        mx = fmaxf(mx, v);
    }
#pragma unroll
    for (int off = 16; off; off >>= 1)
        mx = fmaxf(mx, __shfl_xor_sync(0xffffffffu, mx, off));
    if (lane == 0) red[warp] = mx;
    __syncthreads();
    if (t < 32) {
        float v = (t < 8) ? red[t] : -INFINITY;
#pragma unroll
        for (int off = 4; off; off >>= 1)
            v = fmaxf(v, __shfl_xor_sync(0xffffffffu, v, off));
        if (t == 0) red[0] = v;
    }
    __syncthreads();
    mx = red[0];
    __syncthreads();

    float sum = 0.f;
#pragma unroll
    for (int s = 0; s < 8; ++s) {
        int i = t + s * 256;
        float v = sc[i];
        float e = (v == -INFINITY) ? 0.f : expf(v - mx);
        sc[i] = e;
        sum += e;
    }
#pragma unroll
    for (int off = 16; off; off >>= 1)
        sum += __shfl_xor_sync(0xffffffffu, sum, off);
    if (lane == 0) red[warp] = sum;
    __syncthreads();
    if (t < 32) {
        float v = (t < 8) ? red[t] : 0.f;
#pragma unroll
        for (int off = 4; off; off >>= 1)
            v += __shfl_xor_sync(0xffffffffu, v, off);
        if (t == 0) red[0] = v;
    }
    __syncthreads();
    const float inv = 1.0f / red[0];
#pragma unroll
    for (int s = 0; s < 8; ++s) {
        int i = t + s * 256;
        out[k * NNODES + i] = sc[i] * inv;
    }
}

extern "C" void kernel_launch(void* const* d_in, const int* in_sizes, int n_in,
                              void* d_out, int out_size) {
    const float* ctx  = (const float*)d_in[0];
    const float* node = (const float*)d_in[1];
    const void*  mask = d_in[2];
    const float* Wq   = (const float*)d_in[3];
    const float* Wk   = (const float*)d_in[4];
    float* out = (float*)d_out;
    (void)in_sizes; (void)n_in; (void)out_size;

    detect_mask_kernel<<<1, 256>>>((const int*)mask);
    proj_gemm<false><<<128, 256>>>(ctx, Wq);     // g_cq = ctx @ Wq^T
    proj_gemm<true ><<<128, 256>>>(nullptr, Wk); // g_qt = g_cq @ Wk
    compat_kernel<<<KK * 8, 256>>>(node);
    softmax_kernel<<<KK, 256>>>(mask, out);
}

// round 7
// speedup vs baseline: 1.1388x; 1.0128x over previous
#include <cuda_runtime.h>
#include <math.h>

#define KK 128
#define NNODES 2048
#define DD 512

__device__ float g_cq[KK * DD];        // context @ Wq^T
__device__ float g_qt[KK * DD];        // g_cq @ Wk
__device__ float g_compat[KK * NNODES];

// ---------------------------------------------------------------------------
// Projection GEMMs.
// Out[128,512]: STAGE1==false: out = ctx @ Wq^T (NT). STAGE1==true: out = g_cq @ Wk (NN).
// Grid 128 = 8 k-tiles(16) x 16 n-tiles(32). Block 256 threads (8 warps).
// ---------------------------------------------------------------------------
template<bool STAGE1>
__global__ void __launch_bounds__(256) proj_gemm(const float* __restrict__ Ain,
                                                 const float* __restrict__ B) {
    __shared__ float As[16][129];
    __shared__ float Bs[32][129];

    const float* A  = STAGE1 ? g_cq : Ain;
    float*      Out = STAGE1 ? g_qt : g_cq;

    const int t    = threadIdx.x;
    const int lane = t & 31;
    const int w    = t >> 5;
    const int kt   = (blockIdx.x >> 4) * 16;
    const int n0   = (blockIdx.x & 15) * 32;
    const int k0   = kt + 2 * w;

    float acc0 = 0.f, acc1 = 0.f;

    for (int mt = 0; mt < DD; mt += 128) {
#pragma unroll
        for (int s = 0; s < 8; ++s) {
            int idx = t + s * 256;
            int r = idx >> 7, c = idx & 127;
            As[r][c] = A[(kt + r) * DD + mt + c];
        }
#pragma unroll
        for (int s = 0; s < 16; ++s) {
            int idx = t + s * 256;
            if (!STAGE1) {               // NT: Bs[n][m] = Wq[n0+n][mt+m]
                int n = idx >> 7, c = idx & 127;
                Bs[n][c] = B[(n0 + n) * DD + mt + c];
            } else {                     // NN: Bs[n][m] = Wk[mt+m][n0+n]
                int n = idx & 31, c = idx >> 5;
                Bs[n][c] = B[(mt + c) * DD + n0 + n];
            }
        }
        __syncthreads();

#pragma unroll 8
        for (int m = 0; m < 128; ++m) {
            float b  = Bs[lane][m];
            acc0 += As[2 * w][m] * b;
            acc1 += As[2 * w + 1][m] * b;
        }
        __syncthreads();
    }

    Out[(k0    ) * DD + n0 + lane] = acc0;
    Out[(k0 + 1) * DD + n0 + lane] = acc1;
}

// ---------------------------------------------------------------------------
// Streaming compat: compat[k,i] = tanh(clip(qt[k].x[k,i], -10,10)) / sqrt(D)
// Grid 2048 blocks x 128 threads (4 warps). Global warp g = 4*b + w handles
// 32 contiguous nodes: k = g>>6, i0 = (g&63)*32. Finer block quantum than the
// previous 256-thread/1024-block version -> better tail balance + higher occ.
// ---------------------------------------------------------------------------
__global__ void __launch_bounds__(128) compat_kernel(const float* __restrict__ node) {
    __shared__ float part[4][32][33];   // [warp][node][lane], +1 pad

    const int lane = threadIdx.x & 31;
    const int w    = threadIdx.x >> 5;
    const int g    = blockIdx.x * 4 + w;
    const int k    = g >> 6;
    const int i0   = (g & 63) * 32;

    const float4* q4 = reinterpret_cast<const float4*>(g_qt + k * DD);
    const float4 q0 = q4[lane];
    const float4 q1 = q4[32 + lane];
    const float4 q2 = q4[64 + lane];
    const float4 q3 = q4[96 + lane];

    const float4* base = reinterpret_cast<const float4*>(node)
                       + ((size_t)(k * NNODES + i0) << 7);   // *128 float4/node

#pragma unroll 4
    for (int ii = 0; ii < 32; ++ii) {
        const float4* p = base + ((size_t)ii << 7);
        float4 v0 = __ldcs(p + lane);
        float4 v1 = __ldcs(p + 32 + lane);
        float4 v2 = __ldcs(p + 64 + lane);
        float4 v3 = __ldcs(p + 96 + lane);
        float a0 = v0.x * q0.x + v0.y * q0.y + v0.z * q0.z + v0.w * q0.w;
        float a1 = v1.x * q1.x + v1.y * q1.y + v1.z * q1.z + v1.w * q1.w;
        float a2 = v2.x * q2.x + v2.y * q2.y + v2.z * q2.z + v2.w * q2.w;
        float a3 = v3.x * q3.x + v3.y * q3.y + v3.z * q3.z + v3.w * q3.w;
        part[w][ii][lane] = (a0 + a1) + (a2 + a3);
    }
    __syncwarp();

    // Lane l reduces node l's 32 partials: bank (l + j) % 32 — conflict-free.
    float s0 = 0.f, s1 = 0.f, s2 = 0.f, s3 = 0.f;
#pragma unroll
    for (int j = 0; j < 32; j += 4) {
        s0 += part[w][lane][j];
        s1 += part[w][lane][j + 1];
        s2 += part[w][lane][j + 2];
        s3 += part[w][lane][j + 3];
    }
    float a = (s0 + s1) + (s2 + s3);
    float c = fminf(10.f, fmaxf(-10.f, a));
    g_compat[k * NNODES + i0 + lane] = tanhf(c) * 0.04419417382415922f; // 1/sqrt(512)
}

// ---------------------------------------------------------------------------
// Masked softmax per row, with inline mask-dtype detection.
// Detection: first 512 int32 words all in {0,1}  =>  int32 mask.
// (uint8 serialization passes this with prob 8^-512 — never.)
// ---------------------------------------------------------------------------
__global__ void __launch_bounds__(256) softmax_kernel(const void* __restrict__ maskp,
                                                      float* __restrict__ out) {
    __shared__ float sc[NNODES];
    __shared__ float red[8];
    __shared__ int s_bad;

    const int k = blockIdx.x;
    const int t = threadIdx.x;
    const int lane = t & 31;
    const int warp = t >> 5;
    const int* m32 = reinterpret_cast<const int*>(maskp);
    const unsigned char* m8 = reinterpret_cast<const unsigned char*>(maskp);

    if (t == 0) s_bad = 0;
    __syncthreads();
    {
        int v0 = m32[t], v1 = m32[t + 256];
        bool bad = ((v0 != 0 && v0 != 1) || (v1 != 0 && v1 != 1));
        if (__syncthreads_or(bad)) { if (t == 0) s_bad = 1; }
    }
    __syncthreads();
    const bool mi32 = (s_bad == 0);

    float mx = -INFINITY;
#pragma unroll
    for (int s = 0; s < 8; ++s) {
        int i = t + s * 256;
        bool msk = mi32 ? (m32[k * NNODES + i] != 0) : (m8[k * NNODES + i] != 0);
        float v = msk ? -INFINITY : g_compat[k * NNODES + i];
        sc[i] = v;
        mx = fmaxf(mx, v);
    }
#pragma unroll
    for (int off = 16; off; off >>= 1)
        mx = fmaxf(mx, __shfl_xor_sync(0xffffffffu, mx, off));
    if (lane == 0) red[warp] = mx;
    __syncthreads();
    if (t < 32) {
        float v = (t < 8) ? red[t] : -INFINITY;
#pragma unroll
        for (int off = 4; off; off >>= 1)
            v = fmaxf(v, __shfl_xor_sync(0xffffffffu, v, off));
        if (t == 0) red[0] = v;
    }
    __syncthreads();
    mx = red[0];
    __syncthreads();

    float sum = 0.f;
#pragma unroll
    for (int s = 0; s < 8; ++s) {
        int i = t + s * 256;
        float v = sc[i];
        float e = (v == -INFINITY) ? 0.f : expf(v - mx);
        sc[i] = e;
        sum += e;
    }
#pragma unroll
    for (int off = 16; off; off >>= 1)
        sum += __shfl_xor_sync(0xffffffffu, sum, off);
    if (lane == 0) red[warp] = sum;
    __syncthreads();
    if (t < 32) {
        float v = (t < 8) ? red[t] : 0.f;
#pragma unroll
        for (int off = 4; off; off >>= 1)
            v += __shfl_xor_sync(0xffffffffu, v, off);
        if (t == 0) red[0] = v;
    }
    __syncthreads();
    const float inv = 1.0f / red[0];
#pragma unroll
    for (int s = 0; s < 8; ++s) {
        int i = t + s * 256;
        out[k * NNODES + i] = sc[i] * inv;
    }
}

extern "C" void kernel_launch(void* const* d_in, const int* in_sizes, int n_in,
                              void* d_out, int out_size) {
    const float* ctx  = (const float*)d_in[0];
    const float* node = (const float*)d_in[1];
    const void*  mask = d_in[2];
    const float* Wq   = (const float*)d_in[3];
    const float* Wk   = (const float*)d_in[4];
    float* out = (float*)d_out;
    (void)in_sizes; (void)n_in; (void)out_size;

    proj_gemm<false><<<128, 256>>>(ctx, Wq);     // g_cq = ctx @ Wq^T
    proj_gemm<true ><<<128, 256>>>(nullptr, Wk); // g_qt = g_cq @ Wk
    compat_kernel<<<KK * 16, 128>>>(node);       // 2048 blocks x 4 warps
    softmax_kernel<<<KK, 256>>>(mask, out);
}

// round 8
// speedup vs baseline: 1.2479x; 1.0957x over previous
#include <cuda_runtime.h>
#include <math.h>

#define KK 128
#define NNODES 2048
#define DD 512
#define NSPLIT 4

__device__ float g_p1[NSPLIT * KK * DD];   // split-K partials of ctx @ Wq^T
__device__ float g_p2[NSPLIT * KK * DD];   // split-K partials of cq @ Wk
__device__ float g_compat[KK * NNODES];    // exp(tanh(clip(dot))/sqrt(D)) with mask applied
__device__ float g_wsum[KK * 64];          // per-warp partial row sums (64 chunks of 32)
__device__ int   g_mask_i32;

// ---------------------------------------------------------------------------
// Split-K projection GEMMs. Grid 512 = 16 ntiles(32) x 8 ktiles(16) x 4 splits.
// Each block computes a 16k x 32n tile over one 128-wide m-slice.
//   STAGE1==false: A = ctx, B = Wq (NT), out partials -> g_p1[split]
//   STAGE1==true : A = sum_s g_p1[s], B = Wk (NN), out partials -> g_p2[split]
// Stage 1 block 0 additionally detects mask dtype (512 words, {0,1} => int32).
// ---------------------------------------------------------------------------
template<bool STAGE1>
__global__ void __launch_bounds__(256) proj_gemm_sk(const float* __restrict__ Ain,
                                                    const float* __restrict__ B,
                                                    const int* __restrict__ m32) {
    __shared__ float As[16][129];
    __shared__ float Bs[32][129];

    const int t    = threadIdx.x;
    const int lane = t & 31;
    const int w    = t >> 5;
    const int bx   = blockIdx.x;
    const int n0   = (bx & 15) * 32;
    const int kt   = ((bx >> 4) & 7) * 16;
    const int sp   = bx >> 7;            // split 0..3
    const int mt   = sp * 128;
    const int k0   = kt + 2 * w;

    if (!STAGE1 && bx == 0) {            // mask dtype probe (ordered before compat)
        int v0 = m32[t], v1 = m32[t + 256];
        bool bad = ((v0 != 0 && v0 != 1) || (v1 != 0 && v1 != 1));
        bool any = __syncthreads_or(bad);
        if (t == 0) g_mask_i32 = any ? 0 : 1;
    }

    // As: 16 x 128 (8 elems/thread)
#pragma unroll
    for (int s = 0; s < 8; ++s) {
        int idx = t + s * 256;
        int r = idx >> 7, c = idx & 127;
        if (!STAGE1) {
            As[r][c] = Ain[(kt + r) * DD + mt + c];
        } else {
            int off = (kt + r) * DD + mt + c;
            As[r][c] = g_p1[off] + g_p1[KK * DD + off]
                     + g_p1[2 * KK * DD + off] + g_p1[3 * KK * DD + off];
        }
    }
    // Bs: 32 x 128 (16 elems/thread)
#pragma unroll
    for (int s = 0; s < 16; ++s) {
        int idx = t + s * 256;
        if (!STAGE1) {                   // NT: Bs[n][m] = Wq[n0+n][mt+m]
            int n = idx >> 7, c = idx & 127;
            Bs[n][c] = B[(n0 + n) * DD + mt + c];
        } else {                         // NN: Bs[n][m] = Wk[mt+m][n0+n]
            int n = idx & 31, c = idx >> 5;
            Bs[n][c] = B[(mt + c) * DD + n0 + n];
        }
    }
    __syncthreads();

    float acc0 = 0.f, acc1 = 0.f;
#pragma unroll 8
    for (int m = 0; m < 128; ++m) {
        float b  = Bs[lane][m];
        acc0 += As[2 * w][m] * b;
        acc1 += As[2 * w + 1][m] * b;
    }

    float* Out = STAGE1 ? g_p2 : g_p1;
    Out[(sp * KK + k0    ) * DD + n0 + lane] = acc0;
    Out[(sp * KK + k0 + 1) * DD + n0 + lane] = acc1;
}

// ---------------------------------------------------------------------------
// Streaming compat + fused masked exp + per-warp row-sum partial.
// Grid 2048 x 128 threads. Global warp g: k = g>>6, chunk = g&63, i0 = chunk*32.
// |v| <= tanh(10)/sqrt(512) ~ 0.0442, so exp without max-shift is safe.
// ---------------------------------------------------------------------------
__global__ void __launch_bounds__(128) compat_kernel(const float* __restrict__ node,
                                                     const void* __restrict__ maskp) {
    __shared__ float part[4][32][33];

    const int lane = threadIdx.x & 31;
    const int w    = threadIdx.x >> 5;
    const int g    = blockIdx.x * 4 + w;
    const int k    = g >> 6;
    const int chunk= g & 63;
    const int i0   = chunk * 32;

    // q[k] = sum of 4 stage-2 split partials
    const float4* p2 = reinterpret_cast<const float4*>(g_p2);
    float4 q0, q1, q2, q3;
    {
        const int rs = DD / 4;           // 128 float4 per row
        float4 a0 = p2[(0 * KK + k) * rs + lane];
        float4 b0 = p2[(1 * KK + k) * rs + lane];
        float4 c0 = p2[(2 * KK + k) * rs + lane];
        float4 d0 = p2[(3 * KK + k) * rs + lane];
        q0 = make_float4(a0.x+b0.x+c0.x+d0.x, a0.y+b0.y+c0.y+d0.y,
                         a0.z+b0.z+c0.z+d0.z, a0.w+b0.w+c0.w+d0.w);
        a0 = p2[(0 * KK + k) * rs + 32 + lane];
        b0 = p2[(1 * KK + k) * rs + 32 + lane];
        c0 = p2[(2 * KK + k) * rs + 32 + lane];
        d0 = p2[(3 * KK + k) * rs + 32 + lane];
        q1 = make_float4(a0.x+b0.x+c0.x+d0.x, a0.y+b0.y+c0.y+d0.y,
                         a0.z+b0.z+c0.z+d0.z, a0.w+b0.w+c0.w+d0.w);
        a0 = p2[(0 * KK + k) * rs + 64 + lane];
        b0 = p2[(1 * KK + k) * rs + 64 + lane];
        c0 = p2[(2 * KK + k) * rs + 64 + lane];
        d0 = p2[(3 * KK + k) * rs + 64 + lane];
        q2 = make_float4(a0.x+b0.x+c0.x+d0.x, a0.y+b0.y+c0.y+d0.y,
                         a0.z+b0.z+c0.z+d0.z, a0.w+b0.w+c0.w+d0.w);
        a0 = p2[(0 * KK + k) * rs + 96 + lane];
        b0 = p2[(1 * KK + k) * rs + 96 + lane];
        c0 = p2[(2 * KK + k) * rs + 96 + lane];
        d0 = p2[(3 * KK + k) * rs + 96 + lane];
        q3 = make_float4(a0.x+b0.x+c0.x+d0.x, a0.y+b0.y+c0.y+d0.y,
                         a0.z+b0.z+c0.z+d0.z, a0.w+b0.w+c0.w+d0.w);
    }

    const float4* base = reinterpret_cast<const float4*>(node)
                       + ((size_t)(k * NNODES + i0) << 7);

#pragma unroll 4
    for (int ii = 0; ii < 32; ++ii) {
        const float4* p = base + ((size_t)ii << 7);
        float4 v0 = __ldcs(p + lane);
        float4 v1 = __ldcs(p + 32 + lane);
        float4 v2 = __ldcs(p + 64 + lane);
        float4 v3 = __ldcs(p + 96 + lane);
        float a0 = v0.x * q0.x + v0.y * q0.y + v0.z * q0.z + v0.w * q0.w;
        float a1 = v1.x * q1.x + v1.y * q1.y + v1.z * q1.z + v1.w * q1.w;
        float a2 = v2.x * q2.x + v2.y * q2.y + v2.z * q2.z + v2.w * q2.w;
        float a3 = v3.x * q3.x + v3.y * q3.y + v3.z * q3.z + v3.w * q3.w;
        part[w][ii][lane] = (a0 + a1) + (a2 + a3);
    }
    __syncwarp();

    float s0 = 0.f, s1 = 0.f, s2 = 0.f, s3 = 0.f;
#pragma unroll
    for (int j = 0; j < 32; j += 4) {
        s0 += part[w][lane][j];
        s1 += part[w][lane][j + 1];
        s2 += part[w][lane][j + 2];
        s3 += part[w][lane][j + 3];
    }
    float a = (s0 + s1) + (s2 + s3);
    float c = fminf(10.f, fmaxf(-10.f, a));
    float v = tanhf(c) * 0.04419417382415922f;   // 1/sqrt(512)

    bool msk;
    if (g_mask_i32) {
        msk = reinterpret_cast<const int*>(maskp)[k * NNODES + i0 + lane] != 0;
    } else {
        msk = reinterpret_cast<const unsigned char*>(maskp)[k * NNODES + i0 + lane] != 0;
    }
    float e = msk ? 0.f : __expf(v);
    g_compat[k * NNODES + i0 + lane] = e;

    // warp sum of e -> one partial per chunk (deterministic: fixed tree)
    float ws = e;
#pragma unroll
    for (int off = 16; off; off >>= 1)
        ws += __shfl_xor_sync(0xffffffffu, ws, off);
    if (lane == 0) g_wsum[k * 64 + chunk] = ws;
}

// ---------------------------------------------------------------------------
// Normalize: grid 256 (2 blocks/row) x 256 threads. Deterministic smem tree
// over the 64 per-chunk partials, then scale 1024 floats per block (float4).
// ---------------------------------------------------------------------------
__global__ void __launch_bounds__(256) norm_kernel(float* __restrict__ out) {
    __shared__ float s[64];
    const int b = blockIdx.x;
    const int k = b >> 1;
    const int t = threadIdx.x;

    if (t < 64) s[t] = g_wsum[k * 64 + t];
    __syncthreads();
#pragma unroll
    for (int st = 32; st; st >>= 1) {
        if (t < st) s[t] += s[t + st];
        __syncthreads();
    }
    const float inv = 1.0f / s[0];

    const int base4 = (k * NNODES + (b & 1) * 1024) / 4;
    const float4* c4 = reinterpret_cast<const float4*>(g_compat);
    float4* o4 = reinterpret_cast<float4*>(out);
    float4 v = c4[base4 + t];
    o4[base4 + t] = make_float4(v.x * inv, v.y * inv, v.z * inv, v.w * inv);
}

extern "C" void kernel_launch(void* const* d_in, const int* in_sizes, int n_in,
                              void* d_out, int out_size) {
    const float* ctx  = (const float*)d_in[0];
    const float* node = (const float*)d_in[1];
    const void*  mask = d_in[2];
    const float* Wq   = (const float*)d_in[3];
    const float* Wk   = (const float*)d_in[4];
    float* out = (float*)d_out;
    (void)in_sizes; (void)n_in; (void)out_size;

    proj_gemm_sk<false><<<512, 256>>>(ctx, Wq, (const int*)mask);  // g_p1
    proj_gemm_sk<true ><<<512, 256>>>(nullptr, Wk, nullptr);       // g_p2
    compat_kernel<<<KK * 16, 128>>>(node, mask);                   // exp + partial sums
    norm_kernel<<<256, 256>>>(out);                                // row-normalize
}